// round 8
// baseline (speedup 1.0000x reference)
#include <cuda_runtime.h>
#include <cstdint>
#include <math_constants.h>

#define T_DIM 64
#define B_DIM 32
#define S_DIM 128
#define E_DIM 512
#define Q_DIM 512
#define H_DIM 256

#define GEMM_BK   32
#define GEMM_PAD  36   // floats per smem row (32 data + 4 pad): conflict-free frags

#define FUSED_TT  16   // t's per CTA in fused kernel

// Scratch (device globals — no allocation allowed)
__device__ float g_src_proj[B_DIM * H_DIM * S_DIM];   // [b][h][s]
__device__ float g_q_proj[T_DIM * B_DIM * H_DIM];     // [t][b][h]

__device__ __forceinline__ float ex2f_(float x) {
    float y; asm("ex2.approx.f32 %0, %1;" : "=f"(y) : "f"(x)); return y;
}
__device__ __forceinline__ float tanhf_(float x) {
    float y; asm("tanh.approx.f32 %0, %1;" : "=f"(y) : "f"(x)); return y;
}
__device__ __forceinline__ void mma_tf32(float c[4], const unsigned a[4], const unsigned b[2]) {
    asm volatile(
        "mma.sync.aligned.m16n8k8.row.col.f32.tf32.tf32.f32 "
        "{%0,%1,%2,%3}, {%4,%5,%6,%7}, {%8,%9}, {%0,%1,%2,%3};"
        : "+f"(c[0]), "+f"(c[1]), "+f"(c[2]), "+f"(c[3])
        : "r"(a[0]), "r"(a[1]), "r"(a[2]), "r"(a[3]), "r"(b[0]), "r"(b[1]));
}
__device__ __forceinline__ void cp_async16(uint32_t saddr, const void* gptr) {
    asm volatile("cp.async.cg.shared.global [%0], [%1], 16;" :: "r"(saddr), "l"(gptr));
}

// ---------------------------------------------------------------------------
// Tensor-core projection GEMM — TF32, cp.async double-buffered (unchanged).
// ---------------------------------------------------------------------------
__global__ __launch_bounds__(512) void proj_gemm(
    const float* __restrict__ src, const float* __restrict__ Wsrc, const float* __restrict__ bsrc,
    const float* __restrict__ qv,  const float* __restrict__ Wq,   const float* __restrict__ bq)
{
    extern __shared__ float sm[];
    float* As = sm;                        // [2][128][GEMM_PAD]
    float* Bs = sm + 2 * 128 * GEMM_PAD;   // [2][64][GEMM_PAD]

    const int bx = blockIdx.x;      // 0..47
    const int n0 = blockIdx.y * 64; // h tile base

    const bool is_src = (bx < 32);
    const float* __restrict__ A    = is_src ? (src + (size_t)bx * 128 * E_DIM)
                                            : (qv  + (size_t)(bx - 32) * 128 * Q_DIM);
    const float* __restrict__ W    = is_src ? Wsrc : Wq;
    const float* __restrict__ bias = is_src ? bsrc : bq;

    const int tid  = threadIdx.x;
    const int warp = tid >> 5;
    const int lane = tid & 31;
    const int wm   = (warp & 3) * 32;
    const int wn   = (warp >> 2) * 16;
    const int frow = lane >> 2;
    const int fcol = lane & 3;

    const uint32_t As_base = (uint32_t)__cvta_generic_to_shared(As);
    const uint32_t Bs_base = (uint32_t)__cvta_generic_to_shared(Bs);

    float acc[2][2][4];
#pragma unroll
    for (int i = 0; i < 2; i++)
#pragma unroll
        for (int j = 0; j < 2; j++)
#pragma unroll
            for (int r = 0; r < 4; r++) acc[i][j][r] = 0.f;

    auto load_chunk = [&](int kc, int buf) {
        const int kt = kc * GEMM_BK;
        const uint32_t abuf = As_base + (uint32_t)buf * 128 * GEMM_PAD * 4;
        const uint32_t bbuf = Bs_base + (uint32_t)buf * 64 * GEMM_PAD * 4;
#pragma unroll
        for (int j = 0; j < 2; j++) {
            const int v = tid + j * 512;
            const int r = v >> 3;
            const int c = (v & 7) * 4;
            cp_async16(abuf + (uint32_t)(r * GEMM_PAD + c) * 4,
                       &A[(size_t)r * 512 + kt + c]);
        }
        {
            const int r = tid >> 3;
            const int c = (tid & 7) * 4;
            cp_async16(bbuf + (uint32_t)(r * GEMM_PAD + c) * 4,
                       &W[(size_t)(n0 + r) * 512 + kt + c]);
        }
        asm volatile("cp.async.commit_group;");
    };

    load_chunk(0, 0);

    for (int kc = 0; kc < 16; kc++) {
        if (kc + 1 < 16) {
            load_chunk(kc + 1, (kc + 1) & 1);
            asm volatile("cp.async.wait_group 1;");
        } else {
            asm volatile("cp.async.wait_group 0;");
        }
        __syncthreads();

        const int buf = kc & 1;
        const float* Ab = As + buf * 128 * GEMM_PAD;
        const float* Bb = Bs + buf * 64 * GEMM_PAD;

#pragma unroll
        for (int ks = 0; ks < 4; ks++) {
            const int k0 = ks * 8;
            unsigned ah[2][4];
#pragma unroll
            for (int mf = 0; mf < 2; mf++) {
                const int m = wm + mf * 16;
                ah[mf][0] = __float_as_uint(Ab[(m + frow    ) * GEMM_PAD + k0 + fcol    ]);
                ah[mf][1] = __float_as_uint(Ab[(m + frow + 8) * GEMM_PAD + k0 + fcol    ]);
                ah[mf][2] = __float_as_uint(Ab[(m + frow    ) * GEMM_PAD + k0 + fcol + 4]);
                ah[mf][3] = __float_as_uint(Ab[(m + frow + 8) * GEMM_PAD + k0 + fcol + 4]);
            }
            unsigned bh[2][2];
#pragma unroll
            for (int nf = 0; nf < 2; nf++) {
                const int n = wn + nf * 8;
                bh[nf][0] = __float_as_uint(Bb[(n + frow) * GEMM_PAD + k0 + fcol    ]);
                bh[nf][1] = __float_as_uint(Bb[(n + frow) * GEMM_PAD + k0 + fcol + 4]);
            }
#pragma unroll
            for (int mf = 0; mf < 2; mf++)
#pragma unroll
                for (int nf = 0; nf < 2; nf++)
                    mma_tf32(acc[mf][nf], ah[mf], bh[nf]);
        }
        __syncthreads();
    }

    const int crow = lane >> 2;
    const int ccol = (lane & 3) * 2;

    if (is_src) {
        const int b = bx;
        float* dst = g_src_proj + (size_t)b * H_DIM * S_DIM;
#pragma unroll
        for (int mf = 0; mf < 2; mf++)
#pragma unroll
            for (int nf = 0; nf < 2; nf++) {
                const int s0  = wm + mf * 16 + crow;
                const int h0g = n0 + wn + nf * 8 + ccol;
                dst[(h0g    ) * S_DIM + s0    ] = acc[mf][nf][0] + bias[h0g    ];
                dst[(h0g + 1) * S_DIM + s0    ] = acc[mf][nf][1] + bias[h0g + 1];
                dst[(h0g    ) * S_DIM + s0 + 8] = acc[mf][nf][2] + bias[h0g    ];
                dst[(h0g + 1) * S_DIM + s0 + 8] = acc[mf][nf][3] + bias[h0g + 1];
            }
    } else {
        const int m0 = (bx - 32) * 128;
#pragma unroll
        for (int mf = 0; mf < 2; mf++)
#pragma unroll
            for (int nf = 0; nf < 2; nf++) {
                const int m   = m0 + wm + mf * 16 + crow;
                const int h0g = n0 + wn + nf * 8 + ccol;
                g_q_proj[(size_t)m * H_DIM + h0g    ]       = acc[mf][nf][0] + bias[h0g    ];
                g_q_proj[(size_t)m * H_DIM + h0g + 1]       = acc[mf][nf][1] + bias[h0g + 1];
                g_q_proj[(size_t)(m + 8) * H_DIM + h0g    ] = acc[mf][nf][2] + bias[h0g    ];
                g_q_proj[(size_t)(m + 8) * H_DIM + h0g + 1] = acc[mf][nf][3] + bias[h0g + 1];
            }
    }
}

// ---------------------------------------------------------------------------
// Fused kernel, TT=16: CTA = (t-group of 16, b), grid 4x32 = 128 CTAs (1/SM).
// 512 threads: s = tid&127, hg = tid>>7 (H quarter, 64 h each).
// Per thread: 16 t-accumulators over its 64 h's -> MUFU-duty-optimized.
// Dynamic smem: qs[16][256] | w2s[256] | part[16][4][128] | redm[16][4] | reds[16][4]
// ---------------------------------------------------------------------------
__global__ __launch_bounds__(512) void fused_attn(
    const float* __restrict__ w2, const float* __restrict__ b2p,
    const int* __restrict__ mask, float* __restrict__ out)
{
    extern __shared__ float smf[];
    float* qs   = smf;                         // [16][256]
    float* w2s  = qs + FUSED_TT * H_DIM;       // [256]
    float* part = w2s + H_DIM;                 // [16][4][128]
    float* redm = part + FUSED_TT * 4 * S_DIM; // [16][4]
    float* reds = redm + FUSED_TT * 4;         // [16][4]

    const int b   = blockIdx.y;
    const int tg  = blockIdx.x;            // t = tg*16 + tt
    const int tid = threadIdx.x;
    const int s   = tid & 127;
    const int hg  = tid >> 7;              // 0..3

    const float LOG2E = 1.442695040888963407f;

    // fill qs: 16*256 = 4096 elems, 8 per thread; q_proj row for t is contiguous
    for (int idx = tid; idx < FUSED_TT * H_DIM; idx += 512) {
        const int tt = idx >> 8;
        const int h  = idx & (H_DIM - 1);
        qs[idx] = g_q_proj[((size_t)(tg * FUSED_TT + tt) * B_DIM + b) * H_DIM + h];
    }
    if (tid < H_DIM) w2s[tid] = w2[tid];
    __syncthreads();

    const float* __restrict__ srcb = g_src_proj + (size_t)b * H_DIM * S_DIM + s;
    const int h0 = hg * 64;

    float acc[FUSED_TT];
#pragma unroll
    for (int tt = 0; tt < FUSED_TT; tt++) acc[tt] = 0.f;

#pragma unroll 4
    for (int i = 0; i < 64; i++) {
        const int h = h0 + i;
        const float sv = srcb[h * S_DIM];
        const float w  = w2s[h];
        const float* qh = qs + h;
#pragma unroll
        for (int tt = 0; tt < FUSED_TT; tt++)
            acc[tt] = fmaf(w, tanhf_(sv + qh[tt * H_DIM]), acc[tt]);
    }

#pragma unroll
    for (int tt = 0; tt < FUSED_TT; tt++)
        part[(tt * 4 + hg) * S_DIM + s] = acc[tt];
    __syncthreads();

    // Each (hg, s) finishes softmax for tt in [hg*4, hg*4+4)
    const int lane = tid & 31;
    const int gw   = (tid >> 5) & 3;       // warp-within-group = s/32
    const float b2v = b2p[0];
    const bool masked = (mask[b * S_DIM + s] != 0);

    float logit[4];
#pragma unroll
    for (int j = 0; j < 4; j++) {
        const int tt = hg * 4 + j;
        float lg = ((part[(tt * 4 + 0) * S_DIM + s] + part[(tt * 4 + 1) * S_DIM + s]) +
                    (part[(tt * 4 + 2) * S_DIM + s] + part[(tt * 4 + 3) * S_DIM + s])) + b2v;
        if (masked) lg = __int_as_float(0xff800000);
        logit[j] = lg;

        float m = lg;
#pragma unroll
        for (int off = 16; off >= 1; off >>= 1)
            m = fmaxf(m, __shfl_xor_sync(0xffffffffu, m, off));
        if (lane == 0) redm[tt * 4 + gw] = m;
    }
    __syncthreads();

    float e[4];
#pragma unroll
    for (int j = 0; j < 4; j++) {
        const int tt = hg * 4 + j;
        const float bm = fmaxf(fmaxf(redm[tt * 4 + 0], redm[tt * 4 + 1]),
                               fmaxf(redm[tt * 4 + 2], redm[tt * 4 + 3]));
        e[j] = ex2f_((logit[j] - bm) * LOG2E);
        float sum = e[j];
#pragma unroll
        for (int off = 16; off >= 1; off >>= 1)
            sum += __shfl_xor_sync(0xffffffffu, sum, off);
        if (lane == 0) reds[tt * 4 + gw] = sum;
    }
    __syncthreads();

#pragma unroll
    for (int j = 0; j < 4; j++) {
        const int tt = hg * 4 + j;
        const float tot = (reds[tt * 4 + 0] + reds[tt * 4 + 1]) +
                          (reds[tt * 4 + 2] + reds[tt * 4 + 3]);
        const int t = tg * FUSED_TT + tt;
        out[((size_t)t * B_DIM + b) * S_DIM + s] = e[j] / tot;
    }
}

extern "C" void kernel_launch(void* const* d_in, const int* in_sizes, int n_in,
                              void* d_out, int out_size)
{
    const float* src  = (const float*)d_in[0];
    const int*   mask = (const int*)d_in[1];
    const float* qv   = (const float*)d_in[2];
    const float* Wsrc = (const float*)d_in[3];
    const float* bsrc = (const float*)d_in[4];
    const float* Wq   = (const float*)d_in[5];
    const float* bq   = (const float*)d_in[6];
    const float* w2   = (const float*)d_in[7];
    const float* b2   = (const float*)d_in[8];
    float*       out  = (float*)d_out;

    const int gemm_smem = (2 * 128 * GEMM_PAD + 2 * 64 * GEMM_PAD) * 4;  // 55296
    cudaFuncSetAttribute(proj_gemm, cudaFuncAttributeMaxDynamicSharedMemorySize, gemm_smem);

    const int fused_smem = (FUSED_TT * H_DIM + H_DIM + FUSED_TT * 4 * S_DIM +
                            FUSED_TT * 4 * 2) * 4;  // ~50.7 KB
    cudaFuncSetAttribute(fused_attn, cudaFuncAttributeMaxDynamicSharedMemorySize, fused_smem);

    dim3 g1(48, 4);
    proj_gemm<<<g1, 512, gemm_smem>>>(src, Wsrc, bsrc, qv, Wq, bq);

    dim3 g2(T_DIM / FUSED_TT, B_DIM);
    fused_attn<<<g2, 512, fused_smem>>>(w2, b2, mask, out);
}